// round 1
// baseline (speedup 1.0000x reference)
#include <cuda_runtime.h>
#include <cuda_bf16.h>

#define Nn      50000
#define Ee      800000
#define IN_DIM  512
#define HIDD    256
#define OUTD    64

// ---------------- scratch (device globals; no allocs allowed) ----------------
__device__ float g_H1[(size_t)Nn * HIDD];   // x @ W1
__device__ float g_S1[(size_t)Nn * HIDD];   // relu(spmm(H1)+b1)
__device__ float g_H2[(size_t)Nn * OUTD];   // S1 @ W2
__device__ int   g_cnt[Nn];                 // histogram, then scatter fill cursor
__device__ int   g_rowptr[Nn + 1];
__device__ int   g_ecol[Ee];
__device__ float g_eval[Ee];

// ---------------- CSR build ----------------
__global__ void k_zero_cnt() {
    int i = blockIdx.x * blockDim.x + threadIdx.x;
    if (i < Nn) g_cnt[i] = 0;
}

__global__ void k_hist(const int* __restrict__ rows) {
    int e = blockIdx.x * blockDim.x + threadIdx.x;
    if (e < Ee) atomicAdd(&g_cnt[rows[e]], 1);
}

// single-block exclusive scan over g_cnt -> g_rowptr; re-zeros g_cnt for scatter
__global__ void k_scan() {
    const int T = 1024;
    const int ITEMS = (Nn + T - 1) / T;  // 49
    __shared__ int sA[T], sB[T];
    int tid = threadIdx.x;
    int base = tid * ITEMS;

    int sum = 0;
    for (int i = 0; i < ITEMS; i++) {
        int idx = base + i;
        if (idx < Nn) sum += g_cnt[idx];
    }
    sA[tid] = sum;
    __syncthreads();

    int* in = sA; int* out = sB;
    for (int off = 1; off < T; off <<= 1) {
        out[tid] = in[tid] + (tid >= off ? in[tid - off] : 0);
        __syncthreads();
        int* t = in; in = out; out = t;
    }
    // 'in' holds inclusive scan
    int run = (tid == 0) ? 0 : in[tid - 1];
    for (int i = 0; i < ITEMS; i++) {
        int idx = base + i;
        if (idx < Nn) {
            g_rowptr[idx] = run;
            run += g_cnt[idx];
            g_cnt[idx] = 0;   // reset for scatter fill
        }
    }
    if (tid == T - 1) g_rowptr[Nn] = Ee;
}

__global__ void k_scatter(const int* __restrict__ rows,
                          const int* __restrict__ cols,
                          const float* __restrict__ vals) {
    int e = blockIdx.x * blockDim.x + threadIdx.x;
    if (e >= Ee) return;
    int r = rows[e];
    int pos = g_rowptr[r] + atomicAdd(&g_cnt[r], 1);
    g_ecol[pos] = cols[e];
    g_eval[pos] = vals[e];
}

// ---------------- generic register-tiled SGEMM (row-major A[M,K] * B[K,Nd]) ----------------
template <int BM, int BN, int BK, int TM, int TN>
__device__ __forceinline__ void sgemm_body(const float* __restrict__ A,
                                           const float* __restrict__ B,
                                           float* __restrict__ C,
                                           int M, int K, int Nd) {
    constexpr int THREADS = (BM / TM) * (BN / TN);
    __shared__ float As[BK][BM];
    __shared__ float Bs[BK][BN];

    const int tid = threadIdx.x;
    const int tx = tid % (BN / TN);
    const int ty = tid / (BN / TN);
    const int rowBase = blockIdx.x * BM;
    const int colBase = blockIdx.y * BN;

    float acc[TM][TN];
#pragma unroll
    for (int i = 0; i < TM; i++)
#pragma unroll
        for (int j = 0; j < TN; j++) acc[i][j] = 0.0f;

    constexpr int A_LOADS = (BM * BK) / (THREADS * 4);
    constexpr int B_LOADS = (BK * BN) / (THREADS * 4);

    for (int k0 = 0; k0 < K; k0 += BK) {
#pragma unroll
        for (int l = 0; l < A_LOADS; l++) {
            int e = (tid + l * THREADS) * 4;   // element in BM x BK tile (row-major)
            int r = e / BK, c = e % BK;
            float4 v = make_float4(0.f, 0.f, 0.f, 0.f);
            int gr = rowBase + r;
            if (gr < M) v = *(const float4*)&A[(size_t)gr * K + k0 + c];
            As[c + 0][r] = v.x;
            As[c + 1][r] = v.y;
            As[c + 2][r] = v.z;
            As[c + 3][r] = v.w;
        }
#pragma unroll
        for (int l = 0; l < B_LOADS; l++) {
            int e = (tid + l * THREADS) * 4;   // element in BK x BN tile
            int r = e / BN, c = e % BN;
            float4 v = *(const float4*)&B[(size_t)(k0 + r) * Nd + colBase + c];
            *(float4*)&Bs[r][c] = v;
        }
        __syncthreads();

#pragma unroll
        for (int kk = 0; kk < BK; kk++) {
            float a[TM], b[TN];
#pragma unroll
            for (int i = 0; i < TM; i++) a[i] = As[kk][ty * TM + i];
#pragma unroll
            for (int j = 0; j < TN; j++) b[j] = Bs[kk][tx * TN + j];
#pragma unroll
            for (int i = 0; i < TM; i++)
#pragma unroll
                for (int j = 0; j < TN; j++) acc[i][j] = fmaf(a[i], b[j], acc[i][j]);
        }
        __syncthreads();
    }

#pragma unroll
    for (int i = 0; i < TM; i++) {
        int gr = rowBase + ty * TM + i;
        if (gr >= M) continue;
#pragma unroll
        for (int j = 0; j < TN / 4; j++) {
            int gc = colBase + tx * TN + j * 4;
            float4 v = make_float4(acc[i][j * 4 + 0], acc[i][j * 4 + 1],
                                   acc[i][j * 4 + 2], acc[i][j * 4 + 3]);
            *(float4*)&C[(size_t)gr * Nd + gc] = v;
        }
    }
}

__global__ __launch_bounds__(256) void k_gemm1(const float* __restrict__ x,
                                               const float* __restrict__ W1) {
    sgemm_body<128, 128, 8, 8, 8>(x, W1, g_H1, Nn, IN_DIM, HIDD);
}

__global__ __launch_bounds__(256) void k_gemm2(const float* __restrict__ W2) {
    sgemm_body<128, 64, 16, 8, 4>(g_S1, W2, g_H2, Nn, HIDD, OUTD);
}

// ---------------- SpMM 1: S1 = relu(csr_spmm(H1) + b1), one block per row ----------------
__global__ __launch_bounds__(HIDD) void k_spmm1(const float* __restrict__ b1) {
    int row = blockIdx.x;
    int d = threadIdx.x;
    int s = g_rowptr[row];
    int e = g_rowptr[row + 1];
    float acc = 0.0f;
    int j = s;
    for (; j + 4 <= e; j += 4) {
        int   c0 = g_ecol[j + 0], c1 = g_ecol[j + 1], c2 = g_ecol[j + 2], c3 = g_ecol[j + 3];
        float v0 = g_eval[j + 0], v1 = g_eval[j + 1], v2 = g_eval[j + 2], v3 = g_eval[j + 3];
        float h0 = g_H1[(size_t)c0 * HIDD + d];
        float h1 = g_H1[(size_t)c1 * HIDD + d];
        float h2 = g_H1[(size_t)c2 * HIDD + d];
        float h3 = g_H1[(size_t)c3 * HIDD + d];
        acc = fmaf(v0, h0, acc);
        acc = fmaf(v1, h1, acc);
        acc = fmaf(v2, h2, acc);
        acc = fmaf(v3, h3, acc);
    }
    for (; j < e; j++) {
        acc = fmaf(g_eval[j], g_H1[(size_t)g_ecol[j] * HIDD + d], acc);
    }
    acc += b1[d];
    g_S1[(size_t)row * HIDD + d] = fmaxf(acc, 0.0f);
}

// ---------------- SpMM 2: out = csr_spmm(H2) + b2, 4 rows per 256-thread block ----------------
__global__ __launch_bounds__(256) void k_spmm2(const float* __restrict__ b2,
                                               float* __restrict__ out) {
    int row = blockIdx.x * 4 + (threadIdx.x >> 6);
    int d = threadIdx.x & 63;
    if (row >= Nn) return;
    int s = g_rowptr[row];
    int e = g_rowptr[row + 1];
    float acc = 0.0f;
    int j = s;
    for (; j + 4 <= e; j += 4) {
        int   c0 = g_ecol[j + 0], c1 = g_ecol[j + 1], c2 = g_ecol[j + 2], c3 = g_ecol[j + 3];
        float v0 = g_eval[j + 0], v1 = g_eval[j + 1], v2 = g_eval[j + 2], v3 = g_eval[j + 3];
        acc = fmaf(v0, g_H2[(size_t)c0 * OUTD + d], acc);
        acc = fmaf(v1, g_H2[(size_t)c1 * OUTD + d], acc);
        acc = fmaf(v2, g_H2[(size_t)c2 * OUTD + d], acc);
        acc = fmaf(v3, g_H2[(size_t)c3 * OUTD + d], acc);
    }
    for (; j < e; j++) {
        acc = fmaf(g_eval[j], g_H2[(size_t)g_ecol[j] * OUTD + d], acc);
    }
    out[(size_t)row * OUTD + d] = acc + b2[d];
}

// ---------------- entry point ----------------
extern "C" void kernel_launch(void* const* d_in, const int* in_sizes, int n_in,
                              void* d_out, int out_size) {
    const float* x    = (const float*)d_in[0];
    const int*   rows = (const int*)  d_in[1];
    const int*   cols = (const int*)  d_in[2];
    const float* vals = (const float*)d_in[3];
    const float* W1   = (const float*)d_in[4];
    const float* b1   = (const float*)d_in[5];
    const float* W2   = (const float*)d_in[6];
    const float* b2   = (const float*)d_in[7];
    float* out = (float*)d_out;

    // CSR build
    k_zero_cnt<<<(Nn + 255) / 256, 256>>>();
    k_hist<<<(Ee + 255) / 256, 256>>>(rows);
    k_scan<<<1, 1024>>>();
    k_scatter<<<(Ee + 255) / 256, 256>>>(rows, cols, vals);

    // layer 1
    k_gemm1<<<dim3((Nn + 127) / 128, HIDD / 128), 256>>>(x, W1);
    k_spmm1<<<Nn, HIDD>>>(b1);

    // layer 2
    k_gemm2<<<dim3((Nn + 127) / 128, 1), 256>>>(W2);
    k_spmm2<<<(Nn + 3) / 4, 256>>>(b2, out);
}